// round 6
// baseline (speedup 1.0000x reference)
#include <cuda_runtime.h>
#include <cuda_fp16.h>
#include <math.h>
#include <stdint.h>

// GRU decoder B=2048,H=512,F=128,T=96 via mma.sync fp16 HMMA (fp32 acc).
// One folded GEMM per step: C = h_t @ G^T, G packed (N=2048,K=512),
// col n=4j+g: [r_comb, z_comb, i_n, h_n].
// R6: fp16 2-term split  C = (A1+A2) @ B1  (A hi/lo fp16 -> 2^-22, B fp16
// -> 2^-11) : 2 MMAs instead of 3, B-lo eliminated.
// BM=256,BN=128,BK=32, 512 threads, 4-stage cp.async pipeline (48KB/stage),
// one barrier per stage. One-wave grid (136 CTAs incl. fused output GEMM).

#define Bsz 2048
#define Hsz 512
#define Fsz 128
#define Tsz 96
#define NCHUNK 16           // K=512 / BK=32
#define NSTAGE 4
#define STG 49152           // Ah 16K | Al 16K | B 16K (B rows padded to 128B)
#define SMEMB (NSTAGE * STG)

__device__ __half g_G [2048 * 512];
__device__ __half g_G0[2048 * 512];
__device__ __half g_Fw[128 * 512];
__device__ __half g_Ah[2][2048 * 512];
__device__ __half g_Al[2][2048 * 512];
__device__ float g_hf[2][2048 * 512];
__device__ float g_bias[2048];
__device__ float g_bias0[2048];

__device__ __forceinline__ uint32_t smem_u32(const void* p) {
    uint32_t a;
    asm("{ .reg .u64 t; cvta.to.shared.u64 t, %1; cvt.u32.u64 %0, t; }" : "=r"(a) : "l"(p));
    return a;
}
__device__ __forceinline__ void mma_f16(float* d, const uint32_t* a, uint32_t b0, uint32_t b1) {
    asm volatile(
        "mma.sync.aligned.m16n8k16.row.col.f32.f16.f16.f32 "
        "{%0,%1,%2,%3}, {%4,%5,%6,%7}, {%8,%9}, {%0,%1,%2,%3};"
        : "+f"(d[0]), "+f"(d[1]), "+f"(d[2]), "+f"(d[3])
        : "r"(a[0]), "r"(a[1]), "r"(a[2]), "r"(a[3]), "r"(b0), "r"(b1));
}
__device__ __forceinline__ void ldm4(uint32_t* r, uint32_t addr) {
    asm volatile("ldmatrix.sync.aligned.m8n8.x4.shared.b16 {%0,%1,%2,%3}, [%4];"
                 : "=r"(r[0]), "=r"(r[1]), "=r"(r[2]), "=r"(r[3]) : "r"(addr));
}
__device__ __forceinline__ void cpa16(uint32_t s, const void* g) {
    asm volatile("cp.async.cg.shared.global [%0], [%1], 16;" :: "r"(s), "l"(g));
}
__device__ __forceinline__ void cpa_commit() { asm volatile("cp.async.commit_group;" ::: "memory"); }
__device__ __forceinline__ void cpa_wait2()  { asm volatile("cp.async.wait_group 2;"  ::: "memory"); }

__device__ __forceinline__ void put_split(__half* H, __half* L, int idx, float v) {
    __half h = __float2half_rn(v);
    __half l = __float2half_rn(v - __half2float(h));
    H[idx] = h; L[idx] = l;
}

__global__ void precompute_kernel(const float* __restrict__ w_ih,
                                  const float* __restrict__ w_hh,
                                  const float* __restrict__ b_ih,
                                  const float* __restrict__ b_hh,
                                  const float* __restrict__ fc_w,
                                  const float* __restrict__ fc_b) {
    int r = blockIdx.x;   // 0..1535
    int k = threadIdx.x;  // 0..511
    __shared__ float sw[Fsz], sb[Fsz];
    if (k < Fsz) { sw[k] = w_ih[r * Fsz + k]; sb[k] = fc_b[k]; }
    __syncthreads();
    float acc = 0.f;
    #pragma unroll 8
    for (int f = 0; f < Fsz; f++) acc += sw[f] * fc_w[f * Hsz + k];
    float whh = w_hh[r * Hsz + k];
    int j = r & (Hsz - 1);
    int band = r >> 9;
    if (band == 0) {
        int o = (4 * j + 0) * Hsz + k;
        g_G [o] = __float2half_rn(acc + whh);
        g_G0[o] = __float2half_rn(whh);
    } else if (band == 1) {
        int o = (4 * j + 1) * Hsz + k;
        g_G [o] = __float2half_rn(acc + whh);
        g_G0[o] = __float2half_rn(whh);
    } else {
        int o2 = (4 * j + 2) * Hsz + k;
        g_G [o2] = __float2half_rn(acc);
        g_G0[o2] = __float2half_rn(0.f);
        int o3 = (4 * j + 3) * Hsz + k;
        g_G [o3] = __float2half_rn(whh);
        g_G0[o3] = __float2half_rn(whh);
    }
    if (k == 0) {
        float b2 = 0.f;
        for (int f = 0; f < Fsz; f++) b2 += sw[f] * sb[f];
        float bih = b_ih[r], bhh = b_hh[r];
        if (band == 0) { g_bias[4*j+0] = b2 + bih + bhh; g_bias0[4*j+0] = bih + bhh; }
        else if (band == 1) { g_bias[4*j+1] = b2 + bih + bhh; g_bias0[4*j+1] = bih + bhh; }
        else {
            g_bias [4*j+2] = b2 + bih;  g_bias0[4*j+2] = bih;
            g_bias [4*j+3] = bhh;       g_bias0[4*j+3] = bhh;
        }
    }
}

__global__ void conv_fw_kernel(const float* __restrict__ fc_w) {
    int idx = blockIdx.x * blockDim.x + threadIdx.x;
    g_Fw[idx] = __float2half_rn(fc_w[idx]);
}

__global__ void conv_h0_kernel(const float* __restrict__ hidden) {
    int idx = blockIdx.x * blockDim.x + threadIdx.x;
    float v = hidden[idx];
    g_hf[0][idx] = v;
    put_split(g_Ah[0], g_Al[0], idx, v);
}

// ---- fused step kernel: BM=256, BN=128, BK=32, 512 threads (16 warps 4x4) ----
__global__ __launch_bounds__(512, 1)
void mma_step(int pp, int use0, int ngate, int tout,
              const float* __restrict__ fcb, float* __restrict__ outp) {
    extern __shared__ unsigned char smraw[];
    const uint32_t sb = smem_u32(smraw);

    const int tid = threadIdx.x, wid = tid >> 5, lane = tid & 31;
    const int bx = blockIdx.x;
    const bool outm = (bx >= ngate);
    int mt, nt;
    const __half* B_g;
    if (outm) { mt = bx - ngate; nt = 0; B_g = g_Fw; }
    else {
        mt = bx >> 4; nt = bx & 15;
        B_g = (use0 ? g_G0 : g_G) + nt * 128 * Hsz;
    }
    const __half* Ah_g = g_Ah[pp] + mt * 256 * Hsz;
    const __half* Al_g = g_Al[pp] + mt * 256 * Hsz;

    // A: 256 rows x 8 units (u<4: Ah k-units, u>=4: Al). 4 units/thread.
    // B: 128 rows x 4 units in 128B-padded rows. 1 unit/thread.
    const int ar = tid >> 1;                 // A row
    const int au0 = (tid & 1) * 4;           // first A unit (0 or 4)
    const __half* As_g = (tid & 1) ? Al_g : Ah_g;
    const int br = tid >> 2, bu = tid & 3;   // B row/unit
    const uint32_t bso = br * 128 + (uint32_t)((bu ^ (br & 7)) << 4);
    const int bgo = br * Hsz + bu * 8;

    #define LOAD_STAGE(c) do {                                                  \
        const int koff = (c) * 32;                                              \
        const uint32_t stb = sb + ((c) & (NSTAGE - 1)) * STG;                   \
        _Pragma("unroll")                                                       \
        for (int j = 0; j < 4; j++) {                                           \
            const int u = au0 + j;                                              \
            const uint32_t so = ar * 128 + (uint32_t)((u ^ (ar & 7)) << 4);     \
            cpa16(stb + so, As_g + ar * Hsz + koff + (u & 3) * 8);              \
        }                                                                       \
        cpa16(stb + 32768 + bso, B_g + koff + bgo);                             \
        cpa_commit();                                                           \
    } while (0)

    const int wm0 = (wid >> 2) * 64;
    const int wn0 = (wid & 3) * 32;
    const int r15 = lane & 15;
    const int xr = lane & 7;
    const int ub = lane >> 4;
    uint32_t arow[4], brow[2];
    #pragma unroll
    for (int mb = 0; mb < 4; mb++) arow[mb] = (wm0 + mb * 16 + r15) * 128;
    #pragma unroll
    for (int np = 0; np < 2; np++) brow[np] = 32768u + (wn0 + np * 16 + r15) * 128;

    float acc[4][4][4];
    #pragma unroll
    for (int a = 0; a < 4; a++)
        #pragma unroll
        for (int b = 0; b < 4; b++)
            #pragma unroll
            for (int cc = 0; cc < 4; cc++) acc[a][b][cc] = 0.f;

    LOAD_STAGE(0); LOAD_STAGE(1); LOAD_STAGE(2);

    for (int c = 0; c < NCHUNK; c++) {
        cpa_wait2();
        __syncthreads();
        if (c + 3 < NCHUNK) LOAD_STAGE(c + 3);
        else cpa_commit();                       // keep group count uniform
        const uint32_t base = sb + (c & (NSTAGE - 1)) * STG;
        #pragma unroll
        for (int kk = 0; kk < 2; kk++) {
            const uint32_t uph = (uint32_t)((((kk * 2 + ub)    ) ^ xr) << 4);
            const uint32_t upl = (uint32_t)((((kk * 2 + ub) + 4) ^ xr) << 4);
            uint32_t bf[2][4];
            #pragma unroll
            for (int np = 0; np < 2; np++) ldm4(bf[np], base + brow[np] + uph);
            #pragma unroll
            for (int mb = 0; mb < 4; mb++) {
                uint32_t ah[4], al[4];
                ldm4(ah, base + arow[mb] + uph);
                ldm4(al, base + arow[mb] + upl);
                #pragma unroll
                for (int np = 0; np < 2; np++) {
                    float* a0 = acc[mb][np * 2 + 0];
                    float* a1 = acc[mb][np * 2 + 1];
                    mma_f16(a0, ah, bf[np][0], bf[np][2]);
                    mma_f16(a0, al, bf[np][0], bf[np][2]);
                    mma_f16(a1, ah, bf[np][1], bf[np][3]);
                    mma_f16(a1, al, bf[np][1], bf[np][3]);
                }
            }
        }
    }

    // ---- epilogue ----
    const int trow = lane >> 2, q = lane & 3, qp = q & 1;
    if (!outm) {
        const float* __restrict__ bias = use0 ? g_bias0 : g_bias;
        const float* __restrict__ hfin = g_hf[pp];
        float* __restrict__ hfout = g_hf[pp ^ 1];
        __half* aoh = g_Ah[pp ^ 1];
        __half* aol = g_Al[pp ^ 1];
        #pragma unroll
        for (int mb = 0; mb < 4; mb++) {
            #pragma unroll
            for (int nb = 0; nb < 4; nb++) {
                float c0 = acc[mb][nb][0], c1 = acc[mb][nb][1];
                float c2 = acc[mb][nb][2], c3 = acc[mb][nb][3];
                float rx0 = __shfl_xor_sync(0xffffffffu, c0, 1);
                float rx1 = __shfl_xor_sync(0xffffffffu, c1, 1);
                float rx2 = __shfl_xor_sync(0xffffffffu, c2, 1);
                float rx3 = __shfl_xor_sync(0xffffffffu, c3, 1);
                const int nbase = nt * 128 + wn0 + nb * 8 + (q >> 1) * 4;
                const int j = nbase >> 2;
                const float4 bq = *(const float4*)(bias + nbase);
                const int row = mt * 256 + wm0 + mb * 16 + trow + (qp ? 8 : 0);
                float pr, pz, pn, ph;
                if (qp == 0) { pr = c0 + bq.x; pz = c1 + bq.y; pn = rx0 + bq.z; ph = rx1 + bq.w; }
                else         { pr = rx2 + bq.x; pz = rx3 + bq.y; pn = c2 + bq.z; ph = c3 + bq.w; }
                float rg = 1.f / (1.f + __expf(-pr));
                float zg = 1.f / (1.f + __expf(-pz));
                float ng = tanhf(pn + rg * ph);
                float hold = hfin[row * Hsz + j];
                float hn = (1.f - zg) * ng + zg * hold;
                const int o = row * Hsz + j;
                hfout[o] = hn;
                put_split(aoh, aol, o, hn);
            }
        }
    } else {
        #pragma unroll
        for (int mb = 0; mb < 4; mb++) {
            #pragma unroll
            for (int nb = 0; nb < 4; nb++) {
                const int f = wn0 + nb * 8 + 2 * q;
                const int r0 = mt * 256 + wm0 + mb * 16 + trow;
                const float b0 = fcb[f], b1 = fcb[f + 1];
                float* p0 = outp + (size_t)r0 * (Tsz * Fsz) + (size_t)tout * Fsz + f;
                float* p1 = p0 + 8 * (Tsz * Fsz);
                p0[0] = acc[mb][nb][0] + b0; p0[1] = acc[mb][nb][1] + b1;
                p1[0] = acc[mb][nb][2] + b0; p1[1] = acc[mb][nb][3] + b1;
            }
        }
    }
    #undef LOAD_STAGE
}

extern "C" void kernel_launch(void* const* d_in, const int* in_sizes, int n_in,
                              void* d_out, int out_size) {
    (void)in_sizes; (void)n_in; (void)out_size;
    const float* hidden = (const float*)d_in[0];
    const float* w_ih   = (const float*)d_in[1];
    const float* w_hh   = (const float*)d_in[2];
    const float* b_ih   = (const float*)d_in[3];
    const float* b_hh   = (const float*)d_in[4];
    const float* fc_w   = (const float*)d_in[5];
    const float* fc_b   = (const float*)d_in[6];
    float* outp = (float*)d_out;

    cudaFuncSetAttribute(mma_step, cudaFuncAttributeMaxDynamicSharedMemorySize, SMEMB);

    conv_h0_kernel<<<(Bsz * Hsz) / 256, 256>>>(hidden);
    precompute_kernel<<<3 * Hsz, Hsz>>>(w_ih, w_hh, b_ih, b_hh, fc_w, fc_b);
    conv_fw_kernel<<<(Fsz * Hsz) / 256, 256>>>(fc_w);

    // step 0: x=0 weights (G0), no fused output
    mma_step<<<128, 512, SMEMB>>>(0, 1, 128, 0, fc_b, outp);
    // steps 1..95: gate GEMM for step t + output of step t-1 (row 96-t)
    for (int t = 1; t < Tsz; t++)
        mma_step<<<136, 512, SMEMB>>>(t & 1, 0, 128, Tsz - t, fc_b, outp);
    // final output from h_96 (parity 0), row 0
    mma_step<<<8, 512, SMEMB>>>(0, 0, 0, 0, fc_b, outp);
}

// round 8
// speedup vs baseline: 1.1681x; 1.1681x over previous
#include <cuda_runtime.h>
#include <cuda_fp16.h>
#include <math.h>
#include <stdint.h>

// GRU decoder B=2048,H=512,F=128,T=96. All-register HMMA GEMM:
// no smem, no cp.async, no syncthreads in the step kernel.
// Folded recurrence: one GEMM/step  C = h_t @ G^T, G packed (N=2048,K=512),
// col n=4j+g: [r_comb, z_comb, i_n, h_n]. fp16 2-term split C=(Ah+Al)@B.
//   B: pre-formed MMA fragments in global -> 1 LDG.128 per (n16,k16) per lane.
//   A: interleaved hi/lo fp16 pairs -> LDG.64 per fragment reg pair.
// Output GEMM x = h@fc_w^T fused as 8 extra CTAs (same A, B=fc_w fragments).

#define Bsz 2048
#define Hsz 512
#define Fsz 128
#define Tsz 96

// A pairs: row-major, 256 pairs/row, uint2 = {f16x2 hi(2k,2k+1), f16x2 lo}
__device__ uint2 g_A2[2][Bsz * 256];
// B fragments: [n16blk][kk][lane] -> uint4 (regs r0..r3)
__device__ uint4 g_Gf [128 * 32 * 32];
__device__ uint4 g_G0f[128 * 32 * 32];
__device__ uint4 g_Fwf[  8 * 32 * 32];
__device__ float g_hf[2][Bsz * Hsz];
__device__ float g_bias[2048];
__device__ float g_bias0[2048];

__device__ __forceinline__ void mma_f16(float* d, const uint32_t* a, uint32_t b0, uint32_t b1) {
    asm volatile(
        "mma.sync.aligned.m16n8k16.row.col.f32.f16.f16.f32 "
        "{%0,%1,%2,%3}, {%4,%5,%6,%7}, {%8,%9}, {%0,%1,%2,%3};"
        : "+f"(d[0]), "+f"(d[1]), "+f"(d[2]), "+f"(d[3])
        : "r"(a[0]), "r"(a[1]), "r"(a[2]), "r"(a[3]), "r"(b0), "r"(b1));
}

// fragment half-index for B element (n,k) within a 2048-col-max fragment array
__device__ __forceinline__ int fidx(int n, int k) {
    int blk  = n >> 4, kk = k >> 4;
    int lane = ((n & 7) << 2) | ((k & 7) >> 1);
    int reg  = (((n >> 3) & 1) << 1) | ((k >> 3) & 1);
    return (((blk * 32 + kk) * 32 + lane) * 4 + reg) * 2 + (k & 1);
}

__device__ __forceinline__ uint32_t pack2(float a, float b) {
    __half2 h2 = __floats2half2_rn(a, b);
    return *(uint32_t*)&h2;
}

__global__ void precompute_kernel(const float* __restrict__ w_ih,
                                  const float* __restrict__ w_hh,
                                  const float* __restrict__ b_ih,
                                  const float* __restrict__ b_hh,
                                  const float* __restrict__ fc_w,
                                  const float* __restrict__ fc_b) {
    int r = blockIdx.x;   // 0..1535
    int k = threadIdx.x;  // 0..511
    __shared__ float sw[Fsz], sb[Fsz];
    if (k < Fsz) { sw[k] = w_ih[r * Fsz + k]; sb[k] = fc_b[k]; }
    __syncthreads();
    float acc = 0.f;
    #pragma unroll 8
    for (int f = 0; f < Fsz; f++) acc += sw[f] * fc_w[f * Hsz + k];
    float whh = w_hh[r * Hsz + k];
    int j = r & (Hsz - 1);
    int band = r >> 9;
    __half* G  = (__half*)g_Gf;
    __half* G0 = (__half*)g_G0f;
    if (band == 0) {
        int o = fidx(4 * j + 0, k);
        G [o] = __float2half_rn(acc + whh);
        G0[o] = __float2half_rn(whh);
    } else if (band == 1) {
        int o = fidx(4 * j + 1, k);
        G [o] = __float2half_rn(acc + whh);
        G0[o] = __float2half_rn(whh);
    } else {
        int o2 = fidx(4 * j + 2, k);
        G [o2] = __float2half_rn(acc);
        G0[o2] = __float2half_rn(0.f);
        int o3 = fidx(4 * j + 3, k);
        G [o3] = __float2half_rn(whh);
        G0[o3] = __float2half_rn(whh);
    }
    if (k == 0) {
        float b2 = 0.f;
        for (int f = 0; f < Fsz; f++) b2 += sw[f] * sb[f];
        float bih = b_ih[r], bhh = b_hh[r];
        if (band == 0) { g_bias[4*j+0] = b2 + bih + bhh; g_bias0[4*j+0] = bih + bhh; }
        else if (band == 1) { g_bias[4*j+1] = b2 + bih + bhh; g_bias0[4*j+1] = bih + bhh; }
        else {
            g_bias [4*j+2] = b2 + bih;  g_bias0[4*j+2] = bih;
            g_bias [4*j+3] = bhh;       g_bias0[4*j+3] = bhh;
        }
    }
}

__global__ void conv_fw_kernel(const float* __restrict__ fc_w) {
    int idx = blockIdx.x * blockDim.x + threadIdx.x;  // 128*512
    int n = idx >> 9, k = idx & 511;
    ((__half*)g_Fwf)[fidx(n, k)] = __float2half_rn(fc_w[idx]);
}

__global__ void conv_h0_kernel(const float* __restrict__ hidden) {
    int idx = blockIdx.x * blockDim.x + threadIdx.x;  // 2048*256 pairs
    int row = idx >> 8, p = idx & 255;
    float v0 = hidden[row * Hsz + 2 * p];
    float v1 = hidden[row * Hsz + 2 * p + 1];
    g_hf[0][row * Hsz + 2 * p]     = v0;
    g_hf[0][row * Hsz + 2 * p + 1] = v1;
    __half h0 = __float2half_rn(v0), h1 = __float2half_rn(v1);
    float l0 = v0 - __half2float(h0), l1 = v1 - __half2float(h1);
    uint2 u;
    u.x = pack2(v0, v1);                     // placeholder, fixed below
    u.x = pack2(__half2float(h0), __half2float(h1));
    u.y = pack2(l0, l1);
    g_A2[0][idx] = u;
}

// ---- step kernel: BM=256, BN=128, 512 threads (16 warps, 4x4), no smem ----
__global__ __launch_bounds__(512, 1)
void mma_step(int pp, int use0, int ngate, int tout,
              const float* __restrict__ fcb, float* __restrict__ outp) {
    const int tid = threadIdx.x, wid = tid >> 5, lane = tid & 31;
    const int rq = lane >> 2, q = lane & 3;
    const int bx = blockIdx.x;
    const bool outm = (bx >= ngate);
    int mt, nt;
    const uint4* Bf;
    if (outm) { mt = bx - ngate; nt = 0; Bf = g_Fwf; }
    else {
        mt = bx >> 4; nt = bx & 15;
        Bf = use0 ? g_G0f : g_Gf;
    }
    const int wm0 = (wid >> 2) * 64;
    const int wn0 = (wid & 3) * 32;

    // A pointer: row = mt*256 + wm0 + rq (+mb*16, +8); pair = q (+8kk, +4)
    const uint2* pA = g_A2[pp] + ((mt * 256 + wm0 + rq) * 256 + q);
    // B pointer: blk = nt*8 + wn0/16 (+np); element (blk*32+kk)*32+lane
    const uint4* pB = Bf + ((nt * 8 + (wn0 >> 4)) * 32) * 32 + lane;

    float acc[4][4][4];
    #pragma unroll
    for (int a = 0; a < 4; a++)
        #pragma unroll
        for (int b = 0; b < 4; b++)
            #pragma unroll
            for (int cc = 0; cc < 4; cc++) acc[a][b][cc] = 0.f;

    #pragma unroll 2
    for (int kk = 0; kk < 32; kk++) {
        const uint4 b0 = pB[kk * 32];            // np = 0
        const uint4 b1 = pB[1024 + kk * 32];     // np = 1
        #pragma unroll
        for (int mb = 0; mb < 4; mb++) {
            const uint2* pa = pA + mb * (16 * 256) + kk * 8;
            const uint2 u00 = pa[0];
            const uint2 u10 = pa[8 * 256];
            const uint2 u01 = pa[4];
            const uint2 u11 = pa[8 * 256 + 4];
            uint32_t ah[4] = {u00.x, u10.x, u01.x, u11.x};
            uint32_t al[4] = {u00.y, u10.y, u01.y, u11.y};
            mma_f16(acc[mb][0], ah, b0.x, b0.y);
            mma_f16(acc[mb][0], al, b0.x, b0.y);
            mma_f16(acc[mb][1], ah, b0.z, b0.w);
            mma_f16(acc[mb][1], al, b0.z, b0.w);
            mma_f16(acc[mb][2], ah, b1.x, b1.y);
            mma_f16(acc[mb][2], al, b1.x, b1.y);
            mma_f16(acc[mb][3], ah, b1.z, b1.w);
            mma_f16(acc[mb][3], al, b1.z, b1.w);
        }
    }

    // ---- epilogue ----
    const int trow = rq, qp = q & 1;
    if (!outm) {
        const float* __restrict__ bias = use0 ? g_bias0 : g_bias;
        const float* __restrict__ hfin = g_hf[pp];
        float* __restrict__ hfout = g_hf[pp ^ 1];
        uint2* __restrict__ aout = g_A2[pp ^ 1];
        #pragma unroll
        for (int mb = 0; mb < 4; mb++) {
            #pragma unroll
            for (int nb = 0; nb < 4; nb++) {
                float c0 = acc[mb][nb][0], c1 = acc[mb][nb][1];
                float c2 = acc[mb][nb][2], c3 = acc[mb][nb][3];
                float rx0 = __shfl_xor_sync(0xffffffffu, c0, 1);
                float rx1 = __shfl_xor_sync(0xffffffffu, c1, 1);
                float rx2 = __shfl_xor_sync(0xffffffffu, c2, 1);
                float rx3 = __shfl_xor_sync(0xffffffffu, c3, 1);
                const int nbase = nt * 128 + wn0 + nb * 8 + (q >> 1) * 4;
                const int j = nbase >> 2;
                const float4 bq = *(const float4*)(bias + nbase);
                const int row = mt * 256 + wm0 + mb * 16 + trow + (qp ? 8 : 0);
                float pr, pz, pn, ph;
                if (qp == 0) { pr = c0 + bq.x; pz = c1 + bq.y; pn = rx0 + bq.z; ph = rx1 + bq.w; }
                else         { pr = rx2 + bq.x; pz = rx3 + bq.y; pn = c2 + bq.z; ph = c3 + bq.w; }
                float rg = 1.f / (1.f + __expf(-pr));
                float zg = 1.f / (1.f + __expf(-pz));
                float ng = tanhf(pn + rg * ph);
                float hold = hfin[row * Hsz + j];
                float hn = (1.f - zg) * ng + zg * hold;
                hfout[row * Hsz + j] = hn;
                // pair up (j even from q<2, j odd from partner q^2) and store A2
                float hn_p = __shfl_xor_sync(0xffffffffu, hn, 2);
                if ((q & 2) == 0) {
                    __half h0 = __float2half_rn(hn),   h1 = __float2half_rn(hn_p);
                    float  l0 = hn   - __half2float(h0);
                    float  l1 = hn_p - __half2float(h1);
                    uint2 u;
                    u.x = pack2(__half2float(h0), __half2float(h1));
                    u.y = pack2(l0, l1);
                    aout[row * 256 + (j >> 1)] = u;
                }
            }
        }
    } else {
        #pragma unroll
        for (int mb = 0; mb < 4; mb++) {
            #pragma unroll
            for (int nb = 0; nb < 4; nb++) {
                const int f = wn0 + nb * 8 + 2 * q;
                const int r0 = mt * 256 + wm0 + mb * 16 + trow;
                const float b0 = fcb[f], b1 = fcb[f + 1];
                float* p0 = outp + (size_t)r0 * (Tsz * Fsz) + (size_t)tout * Fsz + f;
                float* p1 = p0 + 8 * (Tsz * Fsz);
                p0[0] = acc[mb][nb][0] + b0; p0[1] = acc[mb][nb][1] + b1;
                p1[0] = acc[mb][nb][2] + b0; p1[1] = acc[mb][nb][3] + b1;
            }
        }
    }
}

extern "C" void kernel_launch(void* const* d_in, const int* in_sizes, int n_in,
                              void* d_out, int out_size) {
    (void)in_sizes; (void)n_in; (void)out_size;
    const float* hidden = (const float*)d_in[0];
    const float* w_ih   = (const float*)d_in[1];
    const float* w_hh   = (const float*)d_in[2];
    const float* b_ih   = (const float*)d_in[3];
    const float* b_hh   = (const float*)d_in[4];
    const float* fc_w   = (const float*)d_in[5];
    const float* fc_b   = (const float*)d_in[6];
    float* outp = (float*)d_out;

    conv_h0_kernel<<<(Bsz * 256) / 256, 256>>>(hidden);
    precompute_kernel<<<3 * Hsz, Hsz>>>(w_ih, w_hh, b_ih, b_hh, fc_w, fc_b);
    conv_fw_kernel<<<(Fsz * Hsz) / 256, 256>>>(fc_w);

    // step 0: x=0 weights (G0), no fused output
    mma_step<<<128, 512>>>(0, 1, 128, 0, fc_b, outp);
    // steps 1..95: gate GEMM for step t + output of step t-1 (row 96-t)
    for (int t = 1; t < Tsz; t++)
        mma_step<<<136, 512>>>(t & 1, 0, 128, Tsz - t, fc_b, outp);
    // final output from h_96 (parity 0), row 0
    mma_step<<<8, 512>>>(0, 0, 0, 0, fc_b, outp);
}